// round 1
// baseline (speedup 1.0000x reference)
#include <cuda_runtime.h>

#define NB 16
#define CD 256
#define HW 4096
#define KA 512
#define ROWS (NB*HW)   // 65536

// Scratch (allocation-free rule: __device__ globals)
__device__ float g_A0[(size_t)ROWS * KA];   // 128 MB: exp(scores/T)
__device__ float g_S[NB * CD * KA];         // 8 MB: gathered, L2-normalized anchors
__device__ float g_invnorm[ROWS];           // per (n,hw) inverse channel norm
__device__ float g_colsum[KA];              // Sinkhorn column-sum accumulator
__device__ float g_cvec[KA];                // Sinkhorn column scaling c

__global__ void zero_colsum_kernel() { g_colsum[threadIdx.x] = 0.0f; }

// ---------------------------------------------------------------- norms
__global__ void norm_kernel(const float* __restrict__ x) {
    int i = blockIdx.x * blockDim.x + threadIdx.x;   // n*HW + hw
    int n = i >> 12;
    int hw = i & 4095;
    const float* p = x + (size_t)n * CD * HW + hw;
    float acc = 0.0f;
#pragma unroll 16
    for (int c = 0; c < CD; ++c) {
        float v = p[(size_t)c * HW];
        acc = fmaf(v, v, acc);
    }
    g_invnorm[i] = 1.0f / fmaxf(sqrtf(acc), 1e-12f);
}

// ---------------------------------------------------------------- anchor gather
__global__ void gather_kernel(const float* __restrict__ x, const int* __restrict__ idx) {
    int t = blockIdx.x * blockDim.x + threadIdx.x;   // n*CD*KA + c*KA + j
    int j  = t & (KA - 1);
    int nc = t >> 9;          // n*CD + c
    int n  = nc >> 8;
    int pos = idx[j];
    g_S[t] = x[(size_t)nc * HW + pos] * g_invnorm[n * HW + pos];
}

// ---------------------------------------------------------------- score GEMM + exp + colsum
// A0[i=n*HW+hw][j] = exp( invnorm[i] * sum_c x[n,c,hw]*S[n,c,j] / T )
// Tiles: BM=128 (hw), BN=128 (j), BK=16 (c); 256 threads, 8x8 microtile.
__global__ __launch_bounds__(256) void score_gemm(const float* __restrict__ x) {
    int n   = blockIdx.z;
    int hw0 = blockIdx.x * 128;
    int j0  = blockIdx.y * 128;
    __shared__ float Xs[16][128];
    __shared__ float Ss[16][128];
    __shared__ float colred[128];
    int tid = threadIdx.x;
    int ty = tid >> 4, tx = tid & 15;
    float acc[8][8];
#pragma unroll
    for (int mi = 0; mi < 8; ++mi)
#pragma unroll
        for (int mj = 0; mj < 8; ++mj) acc[mi][mj] = 0.0f;

    const float* Xbase = x   + (size_t)n * CD * HW + hw0;
    const float* Sbase = g_S + (size_t)n * CD * KA + j0;

    for (int k0 = 0; k0 < CD; k0 += 16) {
#pragma unroll
        for (int it = 0; it < 2; ++it) {
            int idx = tid + 256 * it;     // 0..511 float4 slots
            int row = idx >> 5;           // 0..15 (c)
            int q4  = idx & 31;           // float4 within 128 floats
            float4 v = *(const float4*)(Xbase + (size_t)(k0 + row) * HW + q4 * 4);
            *(float4*)(&Xs[row][q4 * 4]) = v;
            float4 w = *(const float4*)(Sbase + (size_t)(k0 + row) * KA + q4 * 4);
            *(float4*)(&Ss[row][q4 * 4]) = w;
        }
        __syncthreads();
#pragma unroll
        for (int kk = 0; kk < 16; ++kk) {
            float a[8], b[8];
            *(float4*)(a)     = *(float4*)(&Xs[kk][ty * 8]);
            *(float4*)(a + 4) = *(float4*)(&Xs[kk][ty * 8 + 4]);
            *(float4*)(b)     = *(float4*)(&Ss[kk][tx * 8]);
            *(float4*)(b + 4) = *(float4*)(&Ss[kk][tx * 8 + 4]);
#pragma unroll
            for (int mi = 0; mi < 8; ++mi)
#pragma unroll
                for (int mj = 0; mj < 8; ++mj)
                    acc[mi][mj] = fmaf(a[mi], b[mj], acc[mi][mj]);
        }
        __syncthreads();
    }

    // epilogue: exp(score/T), store A0, accumulate column sums (first Sinkhorn colsum)
    if (tid < 128) colred[tid] = 0.0f;
    __syncthreads();
    float colp[8];
#pragma unroll
    for (int mj = 0; mj < 8; ++mj) colp[mj] = 0.0f;
#pragma unroll
    for (int mi = 0; mi < 8; ++mi) {
        int hw = hw0 + ty * 8 + mi;
        int i  = n * HW + hw;
        float sc = g_invnorm[i] * (1.0f / 0.3f);
        float vals[8];
#pragma unroll
        for (int mj = 0; mj < 8; ++mj) {
            float v = __expf(acc[mi][mj] * sc);
            vals[mj] = v;
            colp[mj] += v;
        }
        float* dst = g_A0 + (size_t)i * KA + j0 + tx * 8;
        *(float4*)(dst)     = make_float4(vals[0], vals[1], vals[2], vals[3]);
        *(float4*)(dst + 4) = make_float4(vals[4], vals[5], vals[6], vals[7]);
    }
#pragma unroll
    for (int mj = 0; mj < 8; ++mj) atomicAdd(&colred[tx * 8 + mj], colp[mj]);
    __syncthreads();
    if (tid < 128) atomicAdd(&g_colsum[j0 + tid], colred[tid]);
}

// ---------------------------------------------------------------- c = 1/colsum; reset
__global__ void recip_kernel() {
    int j = threadIdx.x;
    g_cvec[j] = 1.0f / fmaxf(g_colsum[j], 1e-30f);
    g_colsum[j] = 0.0f;
}

// ---------------------------------------------------------------- fused Sinkhorn pass
// For each row i: r_i = 1/(A0_i . c); accumulate colsum_j += r_i * A0_ij.
// 1 warp per row, 16 rows per warp, 128 rows per block.
__global__ __launch_bounds__(256) void sk_pass() {
    __shared__ float cred[KA];
    int tid = threadIdx.x;
    cred[tid] = 0.0f; cred[tid + 256] = 0.0f;
    __syncthreads();
    int warp = tid >> 5, lane = tid & 31;
    float4 c4[4];
#pragma unroll
    for (int m = 0; m < 4; ++m) c4[m] = ((const float4*)g_cvec)[m * 32 + lane];
    float4 ca[4];
#pragma unroll
    for (int m = 0; m < 4; ++m) ca[m] = make_float4(0.f, 0.f, 0.f, 0.f);

    size_t rbase = (size_t)blockIdx.x * 128 + warp * 16;
    for (int t = 0; t < 16; ++t) {
        const float4* row = (const float4*)(g_A0 + (rbase + t) * KA);
        float4 a[4];
        float d = 0.0f;
#pragma unroll
        for (int m = 0; m < 4; ++m) {
            a[m] = row[m * 32 + lane];
            d += a[m].x * c4[m].x + a[m].y * c4[m].y + a[m].z * c4[m].z + a[m].w * c4[m].w;
        }
#pragma unroll
        for (int s = 16; s > 0; s >>= 1) d += __shfl_xor_sync(0xffffffffu, d, s);
        float r = 1.0f / fmaxf(d, 1e-30f);
#pragma unroll
        for (int m = 0; m < 4; ++m) {
            ca[m].x = fmaf(r, a[m].x, ca[m].x);
            ca[m].y = fmaf(r, a[m].y, ca[m].y);
            ca[m].z = fmaf(r, a[m].z, ca[m].z);
            ca[m].w = fmaf(r, a[m].w, ca[m].w);
        }
    }
#pragma unroll
    for (int m = 0; m < 4; ++m) {
        int base = (m * 32 + lane) * 4;
        atomicAdd(&cred[base + 0], ca[m].x);
        atomicAdd(&cred[base + 1], ca[m].y);
        atomicAdd(&cred[base + 2], ca[m].z);
        atomicAdd(&cred[base + 3], ca[m].w);
    }
    __syncthreads();
    atomicAdd(&g_colsum[tid],       cred[tid]);
    atomicAdd(&g_colsum[tid + 256], cred[tid + 256]);
}

// ---------------------------------------------------------------- reconstruct GEMM
// out[n,c,hw] = r_i * sum_j (A0[i,j]*c_j) * S[n,c,j],  r_i = 1/sum_j A0[i,j]*c_j
// Tiles: BM=128 (c), BN=128 (hw), BK=16 (j); rowdot d_i fused into the k-loop.
__global__ __launch_bounds__(256) void recon_gemm(float* __restrict__ out) {
    int n   = blockIdx.z;
    int hw0 = blockIdx.x * 128;
    int c0  = blockIdx.y * 128;
    __shared__ float Ds[16][128];   // S^T tile [j][c]
    __shared__ float Bs[16][128];   // (A0*c)^T tile [j][hw]
    __shared__ float dsum[128];
    int tid = threadIdx.x;
    int ty = tid >> 4, tx = tid & 15;
    float acc[8][8];
#pragma unroll
    for (int mi = 0; mi < 8; ++mi)
#pragma unroll
        for (int mj = 0; mj < 8; ++mj) acc[mi][mj] = 0.0f;
    float dpart = 0.0f;

    const float* Sbase = g_S  + (size_t)n * CD * KA;
    const float* Abase = g_A0 + (size_t)n * HW * KA;

    for (int k0 = 0; k0 < KA; k0 += 16) {
#pragma unroll
        for (int it = 0; it < 2; ++it) {
            int idx = tid + 256 * it;   // 0..511
            int row = idx >> 2;         // 0..127
            int q4  = idx & 3;          // j-float4 within BK
            float4 v = *(const float4*)(Sbase + (size_t)(c0 + row) * KA + k0 + q4 * 4);
            Ds[q4 * 4 + 0][row] = v.x; Ds[q4 * 4 + 1][row] = v.y;
            Ds[q4 * 4 + 2][row] = v.z; Ds[q4 * 4 + 3][row] = v.w;
            float4 cc = *(const float4*)(g_cvec + k0 + q4 * 4);
            float4 w = *(const float4*)(Abase + (size_t)(hw0 + row) * KA + k0 + q4 * 4);
            w.x *= cc.x; w.y *= cc.y; w.z *= cc.z; w.w *= cc.w;
            Bs[q4 * 4 + 0][row] = w.x; Bs[q4 * 4 + 1][row] = w.y;
            Bs[q4 * 4 + 2][row] = w.z; Bs[q4 * 4 + 3][row] = w.w;
        }
        __syncthreads();
        if (tid < 128) {
#pragma unroll
            for (int kk = 0; kk < 16; ++kk) dpart += Bs[kk][tid];
        }
#pragma unroll
        for (int kk = 0; kk < 16; ++kk) {
            float a[8], b[8];
            *(float4*)(a)     = *(float4*)(&Ds[kk][ty * 8]);
            *(float4*)(a + 4) = *(float4*)(&Ds[kk][ty * 8 + 4]);
            *(float4*)(b)     = *(float4*)(&Bs[kk][tx * 8]);
            *(float4*)(b + 4) = *(float4*)(&Bs[kk][tx * 8 + 4]);
#pragma unroll
            for (int mi = 0; mi < 8; ++mi)
#pragma unroll
                for (int mj = 0; mj < 8; ++mj)
                    acc[mi][mj] = fmaf(a[mi], b[mj], acc[mi][mj]);
        }
        __syncthreads();
    }
    if (tid < 128) dsum[tid] = dpart;
    __syncthreads();
    float rin[8];
#pragma unroll
    for (int mj = 0; mj < 8; ++mj) rin[mj] = 1.0f / fmaxf(dsum[tx * 8 + mj], 1e-30f);
#pragma unroll
    for (int mi = 0; mi < 8; ++mi) {
        float* dst = out + (size_t)(n * CD + c0 + ty * 8 + mi) * HW + hw0 + tx * 8;
        *(float4*)(dst)     = make_float4(acc[mi][0] * rin[0], acc[mi][1] * rin[1],
                                          acc[mi][2] * rin[2], acc[mi][3] * rin[3]);
        *(float4*)(dst + 4) = make_float4(acc[mi][4] * rin[4], acc[mi][5] * rin[5],
                                          acc[mi][6] * rin[6], acc[mi][7] * rin[7]);
    }
}

// ----------------------------------------------------------------
extern "C" void kernel_launch(void* const* d_in, const int* in_sizes, int n_in,
                              void* d_out, int out_size) {
    const float* x  = (const float*)d_in[0];
    const int* idx  = (const int*)d_in[1];
    float* out = (float*)d_out;

    zero_colsum_kernel<<<1, KA>>>();
    norm_kernel<<<ROWS / 256, 256>>>(x);
    gather_kernel<<<(NB * CD * KA) / 256, 256>>>(x, idx);
    // score GEMM (writes A0, accumulates colsum for c1)
    score_gemm<<<dim3(HW / 128, KA / 128, NB), 256>>>(x);
    recip_kernel<<<1, KA>>>();   // c1
    // 3 fused Sinkhorn passes -> c2, c3, c4
    for (int it = 0; it < 3; ++it) {
        sk_pass<<<ROWS / 128, 256>>>();
        recip_kernel<<<1, KA>>>();
    }
    // reconstruct (computes r4 on the fly via fused rowdot)
    recon_gemm<<<dim3(HW / 128, CD / 128, NB), 256>>>(out);
}